// round 8
// baseline (speedup 1.0000x reference)
#include <cuda_runtime.h>
#include <cuda_bf16.h>
#include <math.h>
#include <cstdint>

// Problem constants
#define BATCH 4
#define LSEQ 1024
#define EMB 1024
#define NH 16
#define DH 64
#define EH (NH*DH)   // 1024

// ---------------- scratch ----------------
// q,k,v,att,o,rp (21M) + 5 transposed weights (5M)
__device__ float g_scratch[26u * 1024u * 1024u];

// ================= common helpers =================
__device__ __forceinline__ uint32_t smem_u32(const void* p) {
    uint32_t a;
    asm("{ .reg .u64 t; cvta.to.shared.u64 t, %1; cvt.u32.u64 %0, t; }" : "=r"(a) : "l"(p));
    return a;
}
__device__ __forceinline__ void cp16(uint32_t dst, const void* src) {
    asm volatile("cp.async.cg.shared.global [%0], [%1], 16;" :: "r"(dst), "l"(src));
}
#define CP_COMMIT()   asm volatile("cp.async.commit_group;" ::: "memory")
#define CP_WAIT1()    asm volatile("cp.async.wait_group 1;" ::: "memory")
#define CP_WAIT_ALL() asm volatile("cp.async.wait_all;" ::: "memory")

__device__ __forceinline__ void mma_tf32(float* c, const uint32_t* a, const uint32_t* b) {
    asm volatile(
        "mma.sync.aligned.m16n8k8.row.col.f32.tf32.tf32.f32 "
        "{%0,%1,%2,%3}, {%4,%5,%6,%7}, {%8,%9}, {%0,%1,%2,%3};"
        : "+f"(c[0]), "+f"(c[1]), "+f"(c[2]), "+f"(c[3])
        : "r"(a[0]), "r"(a[1]), "r"(a[2]), "r"(a[3]), "r"(b[0]), "r"(b[1]));
}
// ldmatrix x4: 4 m8n8 b16 matrices == tf32 fragments (32-bit word = b16 pair)
__device__ __forceinline__ void ldsm4(uint32_t* r, uint32_t saddr) {
    asm volatile("ldmatrix.sync.aligned.m8n8.x4.shared.b16 {%0,%1,%2,%3}, [%4];"
        : "=r"(r[0]), "=r"(r[1]), "=r"(r[2]), "=r"(r[3]) : "r"(saddr));
}

// ================= merged weight transpose: 5x 1024x1024 =================
__global__ __launch_bounds__(256)
void transpose5(const float* __restrict__ Wq, const float* __restrict__ Wk,
                const float* __restrict__ Wv, const float* __restrict__ Wr,
                const float* __restrict__ Wo, float* __restrict__ dst) {
    __shared__ float t[32][33];
    const float* S = (blockIdx.z == 0) ? Wq : (blockIdx.z == 1) ? Wk :
                     (blockIdx.z == 2) ? Wv : (blockIdx.z == 3) ? Wr : Wo;
    float* D = dst + ((size_t)blockIdx.z << 20);
    const int x = blockIdx.x * 32 + threadIdx.x;
    const int y0 = blockIdx.y * 32;
    #pragma unroll
    for (int i = threadIdx.y; i < 32; i += 8)
        t[i][threadIdx.x] = S[(size_t)(y0 + i) * 1024 + x];
    __syncthreads();
    const int xo = y0 + threadIdx.x;
    #pragma unroll
    for (int i = threadIdx.y; i < 32; i += 8)
        D[(size_t)(blockIdx.x * 32 + i) * 1024 + xo] = t[threadIdx.x][i];
}

// ================= tf32 GEMM: tile 128x256x32, 512 thr, ldmatrix, 3-stage =================
// C[M,N] = A[M,K] @ W[K,N] with W pre-transposed: BT[n][k]. A, BT k-major.
#define GK 1024
#define GN 1024
#define GBM 128
#define GBN 256
#define GBK 32
#define NSTG 3
#define GPAD 36
#define A_STG (GBM * GPAD)             // 4608 floats
#define B_STG (GBN * GPAD)             // 9216 floats
#define STG_FLOATS (A_STG + B_STG)     // 13824
#define GEMM_SMEM_BYTES (NSTG * STG_FLOATS * 4)   // 165888

__device__ __forceinline__ void gemm_tile(const float* __restrict__ A,
                                          const float* __restrict__ BT,
                                          float* __restrict__ C,
                                          int m0, int n0, uint32_t* gsm) {
    const uint32_t sb = smem_u32(gsm);
    const int tid = threadIdx.x;
    const int wid = tid >> 5;
    const int lane = tid & 31;
    const int g = lane >> 2;
    const int t = lane & 3;
    const int lane15 = lane & 15;
    const int kw = (lane >> 4) * 4;      // k word offset 0/4 for ldsm
    const int wm = wid >> 3;             // 0..1 -> 64 m rows
    const int wn = wid & 7;              // 0..7 -> 32 n cols

    const float* Ab = A + (size_t)m0 * GK;
    const float* Bb = BT + (size_t)n0 * GK;

    auto issue = [&](int s) {
        const int k0 = s * GBK;
        const uint32_t abase = sb + (uint32_t)((s % NSTG) * STG_FLOATS * 4);
        const uint32_t bbase = abase + A_STG * 4;
        #pragma unroll
        for (int i = 0; i < 2; i++) {                // A: 1024 chunks
            const int idx = tid + 512 * i;
            const int r = idx >> 3;
            const int c = idx & 7;
            cp16(abase + (uint32_t)(r * (GPAD * 4) + c * 16),
                 Ab + (size_t)r * GK + k0 + c * 4);
        }
        #pragma unroll
        for (int i = 0; i < 4; i++) {                // B: 2048 chunks
            const int idx = tid + 512 * i;
            const int r = idx >> 3;
            const int c = idx & 7;
            cp16(bbase + (uint32_t)(r * (GPAD * 4) + c * 16),
                 Bb + (size_t)r * GK + k0 + c * 4);
        }
        CP_COMMIT();
    };

    float acc[4][4][4];
    #pragma unroll
    for (int mi = 0; mi < 4; mi++)
        #pragma unroll
        for (int ni = 0; ni < 4; ni++)
            #pragma unroll
            for (int r = 0; r < 4; r++) acc[mi][ni][r] = 0.f;

    issue(0);
    issue(1);

    const int nstages = GK / GBK;
    for (int s = 0; s < nstages; s++) {
        CP_WAIT1();
        __syncthreads();
        if (s + 2 < nstages) issue(s + 2);

        const uint32_t sbA = sb + (uint32_t)((s % NSTG) * STG_FLOATS * 4);
        const uint32_t sbB = sbA + A_STG * 4;
        const uint32_t aaddr = sbA + (uint32_t)(((wm * 64 + lane15) * GPAD + kw) * 4);
        const uint32_t baddr = sbB + (uint32_t)(((wn * 32 + lane15) * GPAD + kw) * 4);

        #pragma unroll
        for (int kk = 0; kk < GBK; kk += 8) {
            uint32_t af[4][4], bq[2][4];
            #pragma unroll
            for (int mi = 0; mi < 4; mi++)
                ldsm4(af[mi], aaddr + (uint32_t)((mi * 16 * GPAD + kk) * 4));
            #pragma unroll
            for (int p = 0; p < 2; p++)
                ldsm4(bq[p], baddr + (uint32_t)((p * 16 * GPAD + kk) * 4));
            #pragma unroll
            for (int mi = 0; mi < 4; mi++) {
                #pragma unroll
                for (int ni = 0; ni < 4; ni++) {
                    uint32_t bf[2];
                    bf[0] = (ni & 1) ? bq[ni >> 1][1] : bq[ni >> 1][0];
                    bf[1] = (ni & 1) ? bq[ni >> 1][3] : bq[ni >> 1][2];
                    mma_tf32(acc[mi][ni], af[mi], bf);
                }
            }
        }
        __syncthreads();
    }

    #pragma unroll
    for (int mi = 0; mi < 4; mi++) {
        const int row0 = m0 + wm * 64 + mi * 16 + g;
        #pragma unroll
        for (int ni = 0; ni < 4; ni++) {
            const int col = n0 + wn * 32 + ni * 8 + 2 * t;
            float2 v0 = {acc[mi][ni][0], acc[mi][ni][1]};
            float2 v1 = {acc[mi][ni][2], acc[mi][ni][3]};
            *(float2*)(C + (size_t)row0 * GN + col) = v0;
            *(float2*)(C + (size_t)(row0 + 8) * GN + col) = v1;
        }
    }
}

__global__ __launch_bounds__(512, 1)
void tgemm_proj(const float* __restrict__ w, const float* __restrict__ r,
                const float* __restrict__ WT, float* __restrict__ Cbase) {
    extern __shared__ uint32_t gsm[];
    const int bsel = blockIdx.x >> 2;
    if (bsel == 3 && blockIdx.y >= 8) return;
    const float* A = (bsel < 3) ? w : r;
    const float* BT = WT + ((size_t)bsel << 20);
    float* C = Cbase + (size_t)bsel * (4u << 20);
    gemm_tile(A, BT, C, blockIdx.y * GBM, (blockIdx.x & 3) * GBN, gsm);
}

__global__ __launch_bounds__(512, 1)
void tgemm_single(const float* __restrict__ A, const float* __restrict__ BT,
                  float* __restrict__ C) {
    extern __shared__ uint32_t gsm[];
    gemm_tile(A, BT, C, blockIdx.y * GBM, blockIdx.x * GBN, gsm);
}

// ================= Attention: ring-buffered E/Rt reuse (unchanged from R7) =================
#define PQ 68
#define PE 132
#define OFF_Q   0
#define OFF_K   (OFF_Q  + 64*PQ)
#define OFF_VT  (OFF_K  + 2*64*PQ)
#define OFF_RT  (OFF_VT + 64*PQ)      // 192-row ring
#define OFF_E   (OFF_RT + 192*PQ)     // 128-col ring
#define OFF_S   (OFF_E  + 64*PE)
#define OFF_BK  (OFF_S  + 64*PQ)
#define OFF_BR  (OFF_BK + 64)
#define OFF_RWB (OFF_BR + 128)
#define OFF_RRB (OFF_RWB + 64)
#define OFF_M   (OFF_RRB + 64)
#define OFF_L   (OFF_M + 64)
#define OFF_C   (OFF_L + 64)
#define ATTN_SMEM_FLOATS (OFF_C + 64)
#define ATTN_SMEM_BYTES  (ATTN_SMEM_FLOATS * 4)

__global__ __launch_bounds__(256)
void attn_kernel(const float* __restrict__ q, const float* __restrict__ k,
                 const float* __restrict__ v, const float* __restrict__ rp,
                 const float* __restrict__ rwb, const float* __restrict__ rrb,
                 float* __restrict__ out) {
    extern __shared__ float sm[];
    const uint32_t sb = smem_u32(sm);
    float* sE   = sm + OFF_E;
    float* sS   = sm + OFF_S;
    float* sBK  = sm + OFF_BK;
    float* sBR  = sm + OFF_BR;
    float* sRWB = sm + OFF_RWB;
    float* sRRB = sm + OFF_RRB;
    float* sM   = sm + OFF_M;
    float* sL   = sm + OFF_L;
    float* sC   = sm + OFF_C;
    const uint32_t* Qs  = (const uint32_t*)(sm + OFF_Q);
    const uint32_t* Vts = (const uint32_t*)(sm + OFF_VT);
    const uint32_t* Rts = (const uint32_t*)(sm + OFF_RT);
    const uint32_t* Ss  = (const uint32_t*)(sm + OFF_S);

    const int pair = blockIdx.x;
    const int n  = blockIdx.y;
    const int b  = blockIdx.z;
    const int tid = threadIdx.x;
    const int wid = tid >> 5;
    const int lane = tid & 31;
    const int g = lane >> 2;
    const int t = lane & 3;
    const int mrow = (wid & 3) * 16;
    const int nb32 = (wid >> 2) * 32;
    const int nb64 = (wid >> 2) * 64;

    const size_t bq = (size_t)b * LSEQ * EH;

    const int il = tid >> 2;
    const int sub = tid & 3;
    const int jb = sub * 16;

    if (tid < 64) {
        sRWB[tid] = rwb[n * DH + tid];
        sRRB[tid] = rrb[n * DH + tid];
    }

    for (int half = 0; half < 2; half++) {
        const int itile = (half == 0) ? pair : (15 - pair);
        const int i0 = itile * 64;
        const int ntiles = itile + 1;
        const int mw0 = 960 - i0;

        if (tid < 64) { sM[tid] = -1e30f; sL[tid] = 0.f; }

        float oacc[4][4];
        #pragma unroll
        for (int ni = 0; ni < 4; ni++)
            #pragma unroll
            for (int rr2 = 0; rr2 < 4; rr2++) oacc[ni][rr2] = 0.f;

        #pragma unroll
        for (int i = 0; i < 4; i++) {
            const int idx = tid + 256 * i;
            const int row = idx >> 4;
            const int c = idx & 15;
            cp16(sb + (uint32_t)((OFF_Q + row * PQ) * 4 + c * 16),
                 q + bq + (size_t)(i0 + row) * EH + n * DH + c * 4);
        }
        #pragma unroll
        for (int i = 0; i < 4; i++) {
            const int idx = tid + 256 * i;
            const int row = idx >> 4;
            const int c = idx & 15;
            cp16(sb + (uint32_t)((OFF_K + row * PQ) * 4 + c * 16),
                 k + bq + (size_t)row * EH + n * DH + c * 4);
        }
        #pragma unroll
        for (int i = 0; i < 8; i++) {
            const int idx = tid + 256 * i;
            const int w2 = idx >> 4;
            const int c = idx & 15;
            int m = mw0 + w2;
            if (m > 1023) m = 1023;
            cp16(sb + (uint32_t)((OFF_RT + w2 * PQ) * 4 + c * 16),
                 rp + (size_t)m * EH + n * DH + c * 4);
        }
        CP_COMMIT();

        for (int s = 0; s < ntiles; s++) {
            const int j0 = s * 64;
            const int buf = s & 1;
            const int kofs = OFF_K + buf * 64 * PQ;
            const int sbase = (s & 1) * 64;
            const int ebase = (sbase + 64) & 127;
            const int rtnew = ((s + 1) % 3) * 64;

            if (s + 1 < ntiles) {
                const int nbuf = 1 - buf;
                const int nj0 = j0 + 64;
                #pragma unroll
                for (int i = 0; i < 4; i++) {
                    const int idx = tid + 256 * i;
                    const int row = idx >> 4;
                    const int c = idx & 15;
                    cp16(sb + (uint32_t)((OFF_K + nbuf * 64 * PQ + row * PQ) * 4 + c * 16),
                         k + bq + (size_t)(nj0 + row) * EH + n * DH + c * 4);
                }
                const int nslot = ((s + 2) % 3) * 64;
                const int mb = mw0 + 64 * s + 128;
                #pragma unroll
                for (int i = 0; i < 4; i++) {
                    const int idx = tid + 256 * i;
                    const int row = idx >> 4;
                    const int c = idx & 15;
                    int m = mb + row;
                    if (m > 1023) m = 1023;
                    cp16(sb + (uint32_t)((OFF_RT + (nslot + row) * PQ) * 4 + c * 16),
                         rp + (size_t)m * EH + n * DH + c * 4);
                }
                CP_COMMIT();
            }

            {
                const int jj = tid & 63;
                const int db = (tid >> 6) * 16;
                const float* vrow = v + bq + (size_t)(j0 + jj) * EH + n * DH;
                #pragma unroll
                for (int c = 0; c < 4; c++) {
                    const int d0 = db + c * 4;
                    float4 val = *(const float4*)(vrow + d0);
                    sm[OFF_VT + (d0 + 0) * PQ + jj] = val.x;
                    sm[OFF_VT + (d0 + 1) * PQ + jj] = val.y;
                    sm[OFF_VT + (d0 + 2) * PQ + jj] = val.z;
                    sm[OFF_VT + (d0 + 3) * PQ + jj] = val.w;
                }
            }

            if (s + 1 < ntiles) CP_WAIT1(); else CP_WAIT_ALL();
            __syncthreads();

            const uint32_t* Ks = (const uint32_t*)(sm + kofs);

            {
                float gacc[4][4];
                #pragma unroll
                for (int ni = 0; ni < 4; ni++)
                    #pragma unroll
                    for (int rr2 = 0; rr2 < 4; rr2++) gacc[ni][rr2] = 0.f;
                #pragma unroll
                for (int kk = 0; kk < 64; kk += 8) {
                    uint32_t af[4];
                    af[0] = Qs[(mrow + g) * PQ + kk + t];
                    af[1] = Qs[(mrow + g + 8) * PQ + kk + t];
                    af[2] = Qs[(mrow + g) * PQ + kk + t + 4];
                    af[3] = Qs[(mrow + g + 8) * PQ + kk + t + 4];
                    #pragma unroll
                    for (int ni = 0; ni < 4; ni++) {
                        uint32_t bf[2];
                        const int col0 = nb32 + ni * 8 + g;
                        bf[0] = Ks[col0 * PQ + kk + t];
                        bf[1] = Ks[col0 * PQ + kk + t + 4];
                        mma_tf32(gacc[ni], af, bf);
                    }
                }
                #pragma unroll
                for (int ni = 0; ni < 4; ni++) {
                    const int col = nb32 + ni * 8 + 2 * t;
                    *(float2*)&sS[(mrow + g) * PQ + col] = make_float2(gacc[ni][0], gacc[ni][1]);
                    *(float2*)&sS[(mrow + g + 8) * PQ + col] = make_float2(gacc[ni][2], gacc[ni][3]);
                }
            }

            if (s == 0) {
                float eacc[8][4];
                #pragma unroll
                for (int ni = 0; ni < 8; ni++)
                    #pragma unroll
                    for (int rr2 = 0; rr2 < 4; rr2++) eacc[ni][rr2] = 0.f;
                #pragma unroll
                for (int kk = 0; kk < 64; kk += 8) {
                    uint32_t af[4];
                    af[0] = Qs[(mrow + g) * PQ + kk + t];
                    af[1] = Qs[(mrow + g + 8) * PQ + kk + t];
                    af[2] = Qs[(mrow + g) * PQ + kk + t + 4];
                    af[3] = Qs[(mrow + g + 8) * PQ + kk + t + 4];
                    #pragma unroll
                    for (int ni = 0; ni < 8; ni++) {
                        uint32_t bf[2];
                        const int col0 = nb64 + ni * 8 + g;
                        bf[0] = Rts[col0 * PQ + kk + t];
                        bf[1] = Rts[col0 * PQ + kk + t + 4];
                        mma_tf32(eacc[ni], af, bf);
                    }
                }
                #pragma unroll
                for (int ni = 0; ni < 8; ni++) {
                    const int col = nb64 + ni * 8 + 2 * t;
                    *(float2*)&sE[(mrow + g) * PE + col] = make_float2(eacc[ni][0], eacc[ni][1]);
                    *(float2*)&sE[(mrow + g + 8) * PE + col] = make_float2(eacc[ni][2], eacc[ni][3]);
                }
            } else {
                float eacc[4][4];
                #pragma unroll
                for (int ni = 0; ni < 4; ni++)
                    #pragma unroll
                    for (int rr2 = 0; rr2 < 4; rr2++) eacc[ni][rr2] = 0.f;
                #pragma unroll
                for (int kk = 0; kk < 64; kk += 8) {
                    uint32_t af[4];
                    af[0] = Qs[(mrow + g) * PQ + kk + t];
                    af[1] = Qs[(mrow + g + 8) * PQ + kk + t];
                    af[2] = Qs[(mrow + g) * PQ + kk + t + 4];
                    af[3] = Qs[(mrow + g + 8) * PQ + kk + t + 4];
                    #pragma unroll
                    for (int ni = 0; ni < 4; ni++) {
                        uint32_t bf[2];
                        const int colb = nb32 + ni * 8 + g;
                        bf[0] = Rts[(rtnew + colb) * PQ + kk + t];
                        bf[1] = Rts[(rtnew + colb) * PQ + kk + t + 4];
                        mma_tf32(eacc[ni], af, bf);
                    }
                }
                #pragma unroll
                for (int ni = 0; ni < 4; ni++) {
                    const int col = ebase + nb32 + ni * 8 + 2 * t;
                    *(float2*)&sE[(mrow + g) * PE + col] = make_float2(eacc[ni][0], eacc[ni][1]);
                    *(float2*)&sE[(mrow + g + 8) * PE + col] = make_float2(eacc[ni][2], eacc[ni][3]);
                }
            }

            if (tid < 64) {
                float sv = 0.f;
                const float* kr = sm + kofs + tid * PQ;
                #pragma unroll 16
                for (int d = 0; d < 64; d++) sv += sRWB[d] * kr[d];
                sBK[tid] = sv;
            } else if (s == 0 ? (tid < 192) : (tid < 128)) {
                const int d0 = tid - 64;
                const int eslot = (s == 0) ? d0 : (ebase + d0);
                const int rtrow = (s == 0) ? d0 : (rtnew + d0);
                float sv = 0.f;
                const float* rr2 = sm + OFF_RT + rtrow * PQ;
                #pragma unroll 16
                for (int d = 0; d < 64; d++) sv += sRRB[d] * rr2[d];
                sBR[eslot] = sv;
            }
            __syncthreads();

            {
                float rs[16];
                float mx = -1e30f;
                #pragma unroll
                for (int c = 0; c < 16; c++) {
                    const int jl = jb + c;
                    const int w2 = 63 + jl - il;
                    const int slot = (sbase + w2) & 127;
                    float sv = (sS[il * PQ + jl] + sBK[jl] + sE[il * PE + slot] + sBR[slot]) * 0.03125f;
                    if (j0 + jl > i0 + il) sv = -1e30f;
                    rs[c] = sv;
                    mx = fmaxf(mx, sv);
                }
                mx = fmaxf(mx, __shfl_xor_sync(0xffffffffu, mx, 1));
                mx = fmaxf(mx, __shfl_xor_sync(0xffffffffu, mx, 2));
                const float mold = sM[il];
                const float m = fmaxf(mx, mold);
                float sum = 0.f;
                #pragma unroll
                for (int c = 0; c < 16; c++) {
                    const float p = __expf(rs[c] - m);
                    sS[il * PQ + jb + c] = p;
                    sum += p;
                }
                sum += __shfl_xor_sync(0xffffffffu, sum, 1);
                sum += __shfl_xor_sync(0xffffffffu, sum, 2);
                if (sub == 0) {
                    const float corr = __expf(mold - m);
                    sL[il] = sL[il] * corr + sum;
                    sM[il] = m;
                    sC[il] = corr;
                }
            }
            __syncthreads();

            {
                const float c0 = sC[mrow + g];
                const float c1 = sC[mrow + g + 8];
                #pragma unroll
                for (int ni = 0; ni < 4; ni++) {
                    oacc[ni][0] *= c0; oacc[ni][1] *= c0;
                    oacc[ni][2] *= c1; oacc[ni][3] *= c1;
                }
                #pragma unroll
                for (int kk = 0; kk < 64; kk += 8) {
                    uint32_t af[4];
                    af[0] = Ss[(mrow + g) * PQ + kk + t];
                    af[1] = Ss[(mrow + g + 8) * PQ + kk + t];
                    af[2] = Ss[(mrow + g) * PQ + kk + t + 4];
                    af[3] = Ss[(mrow + g + 8) * PQ + kk + t + 4];
                    #pragma unroll
                    for (int ni = 0; ni < 4; ni++) {
                        uint32_t bf[2];
                        const int col0 = nb32 + ni * 8 + g;
                        bf[0] = Vts[col0 * PQ + kk + t];
                        bf[1] = Vts[col0 * PQ + kk + t + 4];
                        mma_tf32(oacc[ni], af, bf);
                    }
                }
            }
            __syncthreads();
        }

        const float inv0 = 1.f / sL[mrow + g];
        const float inv1 = 1.f / sL[mrow + g + 8];
        const int gi0 = i0 + mrow + g;
        #pragma unroll
        for (int ni = 0; ni < 4; ni++) {
            const int col = nb32 + ni * 8 + 2 * t;
            *(float2*)(out + bq + (size_t)gi0 * EH + n * DH + col) =
                make_float2(oacc[ni][0] * inv0, oacc[ni][1] * inv0);
            *(float2*)(out + bq + (size_t)(gi0 + 8) * EH + n * DH + col) =
                make_float2(oacc[ni][2] * inv1, oacc[ni][3] * inv1);
        }
        __syncthreads();
    }
}

// ---------------- Residual + LayerNorm ----------------
__global__ __launch_bounds__(256)
void ln_kernel(const float* __restrict__ w, const float* __restrict__ o,
               const float* __restrict__ gamma, const float* __restrict__ beta,
               float* __restrict__ out) {
    __shared__ float sh[16];
    __shared__ float mu_s, rstd_s;
    const int row = blockIdx.x;
    const int tid = threadIdx.x;
    const float* wr = w + (size_t)row * EMB;
    const float* orr = o + (size_t)row * EMB;

    float4 xw = *(const float4*)(wr + tid * 4);
    float4 xo = *(const float4*)(orr + tid * 4);
    float x0 = xw.x + xo.x, x1 = xw.y + xo.y, x2 = xw.z + xo.z, x3 = xw.w + xo.w;
    float s = x0 + x1 + x2 + x3;
    float ss = x0 * x0 + x1 * x1 + x2 * x2 + x3 * x3;

    #pragma unroll
    for (int off = 16; off; off >>= 1) {
        s  += __shfl_xor_sync(0xffffffffu, s, off);
        ss += __shfl_xor_sync(0xffffffffu, ss, off);
    }
    if ((tid & 31) == 0) {
        sh[tid >> 5] = s;
        sh[8 + (tid >> 5)] = ss;
    }
    __syncthreads();
    if (tid == 0) {
        float S = 0.f, SS = 0.f;
        #pragma unroll
        for (int i = 0; i < 8; i++) { S += sh[i]; SS += sh[8 + i]; }
        float mu = S * (1.f / 1024.f);
        float var = SS * (1.f / 1024.f) - mu * mu;
        mu_s = mu;
        rstd_s = rsqrtf(var + 1e-3f);
    }
    __syncthreads();

    float mu = mu_s, rstd = rstd_s;
    float4 g4 = *(const float4*)(gamma + tid * 4);
    float4 b4 = *(const float4*)(beta + tid * 4);
    float4 y;
    y.x = (x0 - mu) * rstd * g4.x + b4.x;
    y.y = (x1 - mu) * rstd * g4.y + b4.y;
    y.z = (x2 - mu) * rstd * g4.z + b4.z;
    y.w = (x3 - mu) * rstd * g4.w + b4.w;
    *(float4*)(out + (size_t)row * EMB + tid * 4) = y;
}

// ---------------- launch ----------------
extern "C" void kernel_launch(void* const* d_in, const int* in_sizes, int n_in,
                              void* d_out, int out_size) {
    const float* w     = (const float*)d_in[0];
    const float* r     = (const float*)d_in[1];
    const float* rwb   = (const float*)d_in[2];
    const float* rrb   = (const float*)d_in[3];
    // d_in[4] = attn_mask (causal, analytic)
    const float* Wq    = (const float*)d_in[5];
    const float* Wk    = (const float*)d_in[6];
    const float* Wv    = (const float*)d_in[7];
    const float* Wr    = (const float*)d_in[8];
    const float* Wo    = (const float*)d_in[9];
    const float* gamma = (const float*)d_in[10];
    const float* beta  = (const float*)d_in[11];
    float* outp = (float*)d_out;

    float* base;
    cudaGetSymbolAddress((void**)&base, g_scratch);
    float* gq   = base;
    float* gk   = base + (4u  << 20);
    float* gv   = base + (8u  << 20);
    float* grp  = base + (12u << 20);
    float* gatt = base + (13u << 20);
    float* go   = base + (17u << 20);
    float* WT   = base + (21u << 20);   // 5 transposed weights

    cudaFuncSetAttribute(attn_kernel, cudaFuncAttributeMaxDynamicSharedMemorySize,
                         ATTN_SMEM_BYTES);
    cudaFuncSetAttribute(tgemm_proj, cudaFuncAttributeMaxDynamicSharedMemorySize,
                         GEMM_SMEM_BYTES);
    cudaFuncSetAttribute(tgemm_single, cudaFuncAttributeMaxDynamicSharedMemorySize,
                         GEMM_SMEM_BYTES);

    transpose5<<<dim3(32, 32, 5), dim3(32, 8)>>>(Wq, Wk, Wv, Wr, Wo, WT);

    tgemm_proj<<<dim3(16, 32), 512, GEMM_SMEM_BYTES>>>(w, r, WT, base);

    attn_kernel<<<dim3(8, NH, BATCH), 256, ATTN_SMEM_BYTES>>>(
        gq, gk, gv, grp, rwb, rrb, gatt);

    tgemm_single<<<dim3(EMB / GBN, (BATCH * LSEQ) / GBM), 512, GEMM_SMEM_BYTES>>>(
        gatt, WT + (4u << 20), go);
    ln_kernel<<<BATCH * LSEQ, 256>>>(w, go, gamma, beta, outp);
}